// round 11
// baseline (speedup 1.0000x reference)
#include <cuda_runtime.h>
#include <cuda_fp16.h>

// FWHT-4096 fp32. 256 threads/CTA, 2 rows/CTA. Radix-16 x 3 rounds.
// Exchanges stored as __half2 (row0,row1 packed): smem bytes halved vs fp32.
// SINGLE smem layout S1 for both exchanges (R2 writes back in place), so only
// TWO __syncthreads. S1(e): bits2-3 ^= (e>>5)&3, bit4 ^= (e>>8)&1.
// Conflict-free on all passes: X1 write (4x STS.128), R2 read/write (in place),
// R3 read (bank = lane bits XOR warp-constant + (k&1) half-split).
// fp16 roundoff ~3e-4 total (threshold 1e-3). 6 CTAs/SM forced for occupancy.

#define FWHT_N 4096
#define TPB    256

__device__ __forceinline__ void butterfly16(float v[16]) {
#pragma unroll
    for (int b = 1; b < 16; b <<= 1) {
#pragma unroll
        for (int k = 0; k < 16; k++) {
            if (!(k & b)) {
                float a = v[k];
                float c = v[k | b];
                v[k]     = a + c;
                v[k | b] = a - c;
            }
        }
    }
}

__global__ __launch_bounds__(TPB, 6)
void QHadamard_40243843564239_kernel(const float* __restrict__ x,
                                     float* __restrict__ out) {
    __shared__ __half2 s[FWHT_N];   // 16 KB

    const int t = threadIdx.x;
    const int i = t & 15;
    const int w = t >> 4;
    const int wbit = w & 1;

    const size_t row0 = (size_t)blockIdx.x * 2;
    const float* __restrict__ xin0  = x   + row0 * FWHT_N;
    const float* __restrict__ xin1  = xin0 + FWHT_N;
    float* __restrict__       yout0 = out + row0 * FWHT_N;
    float* __restrict__       yout1 = yout0 + FWHT_N;

    float v0[16], v1[16];

    // ---- Round 1: bits 0..3 in regs. e = 16t + k. 8x LDG.128 front-batched. ----
    {
        const float4* __restrict__ a4 = reinterpret_cast<const float4*>(xin0 + 16 * t);
        const float4* __restrict__ b4 = reinterpret_cast<const float4*>(xin1 + 16 * t);
        float4 fa[4], fb[4];
#pragma unroll
        for (int q = 0; q < 4; q++) fa[q] = __ldcs(a4 + q);
#pragma unroll
        for (int q = 0; q < 4; q++) fb[q] = __ldcs(b4 + q);
#pragma unroll
        for (int q = 0; q < 4; q++) {
            v0[4*q+0] = fa[q].x; v0[4*q+1] = fa[q].y; v0[4*q+2] = fa[q].z; v0[4*q+3] = fa[q].w;
            v1[4*q+0] = fb[q].x; v1[4*q+1] = fb[q].y; v1[4*q+2] = fb[q].z; v1[4*q+3] = fb[q].w;
        }
    }
    butterfly16(v0);
    butterfly16(v1);

    // ---- X1 write: 4x STS.128 (uint4 = 4 half2 slots = elems 4q..4q+3). ----
    // unit index u = 4*t' + (q ^ ((t>>1)&3)),  t' = t ^ ((t>>4)&1).
    {
        uint4* s16 = reinterpret_cast<uint4*>(s);
        const int tp   = t ^ ((t >> 4) & 1);
        const int swz  = (t >> 1) & 3;
        const int base = 4 * tp;
#pragma unroll
        for (int q = 0; q < 4; q++) {
            __half2 h0 = __floats2half2_rn(v0[4*q+0], v1[4*q+0]);
            __half2 h1 = __floats2half2_rn(v0[4*q+1], v1[4*q+1]);
            __half2 h2 = __floats2half2_rn(v0[4*q+2], v1[4*q+2]);
            __half2 h3 = __floats2half2_rn(v0[4*q+3], v1[4*q+3]);
            uint4 u;
            u.x = *reinterpret_cast<unsigned*>(&h0);
            u.y = *reinterpret_cast<unsigned*>(&h1);
            u.z = *reinterpret_cast<unsigned*>(&h2);
            u.w = *reinterpret_cast<unsigned*>(&h3);
            s16[base + (q ^ swz)] = u;
        }
    }
    __syncthreads();

    // ---- Round 2: bits 4..7 in regs. e = i + 16j + 256w. ----
    // S1 = (i&3) + 4*((i>>2) ^ ((j>>1)&3)) + 16*(j ^ wbit) + 256*w   (CF)
    // Read, butterfly, write back to the SAME addresses (thread-private):
    // no barrier between read and write.
    {
        const int ilo = i & 3;
        const int ihi = i >> 2;
        const int base = 256 * w;
#pragma unroll
        for (int j = 0; j < 16; j++) {
            const int idx = ilo + ((ihi ^ ((j >> 1) & 3)) << 2) + ((j ^ wbit) << 4) + base;
            float2 f = __half22float2(s[idx]);
            v0[j] = f.x;
            v1[j] = f.y;
        }
        butterfly16(v0);
        butterfly16(v1);
#pragma unroll
        for (int j = 0; j < 16; j++) {
            const int idx = ilo + ((ihi ^ ((j >> 1) & 3)) << 2) + ((j ^ wbit) << 4) + base;
            s[idx] = __floats2half2_rn(v0[j], v1[j]);
        }
    }
    __syncthreads();

    // ---- Round 3: bits 8..11 in regs. e = t + 256k, still in S1 layout. ----
    // S1(e): bits0-1 = t&3; bits2-3 = ((t>>2)&3) ^ ((t>>5)&3) (warp-constant XOR);
    //        bit4 = ((t>>4)&1) ^ (k&1); bits5+ = (t & ~31) + 256k.  (CF)
    {
        const int lo  = (t & 3) + (((((t >> 2) & 3) ^ ((t >> 5) & 3))) << 2);
        const int b4  = (t >> 4) & 1;
        const int hi  = (t & ~31);
#pragma unroll
        for (int k = 0; k < 16; k++) {
            const int idx = lo + ((b4 ^ (k & 1)) << 4) + hi + (k << 8);
            float2 f = __half22float2(s[idx]);
            v0[k] = f.x;
            v1[k] = f.y;
        }
    }
    butterfly16(v0);
    butterfly16(v1);

    // ---- Store: coalesced streaming STG.32 per row. ----
    const float scale = 0.015625f;   // 1/sqrt(4096)
#pragma unroll
    for (int k = 0; k < 16; k++) {
        __stcs(&yout0[t + 256 * k], v0[k] * scale);
        __stcs(&yout1[t + 256 * k], v1[k] * scale);
    }
}

extern "C" void kernel_launch(void* const* d_in, const int* in_sizes, int n_in,
                              void* d_out, int out_size) {
    const float* x = (const float*)d_in[0];
    float* out = (float*)d_out;
    const int rows = in_sizes[0] / FWHT_N;   // 8192
    QHadamard_40243843564239_kernel<<<rows / 2, TPB>>>(x, out);
}

// round 12
// speedup vs baseline: 1.0502x; 1.0502x over previous
#include <cuda_runtime.h>
#include <cuda_fp16.h>

// FWHT-4096 fp32. 256 threads/CTA, 2 rows/CTA. Radix-16 x 3 rounds.
// Exchanges stored as __half2 (row0,row1 packed): smem bytes halved vs fp32.
// SINGLE smem layout S1 for both exchanges (R2 reads+writes in place): only
// TWO __syncthreads. S1(e): bits2-3 ^= (e>>5)&3, bit4 ^= (e>>8)&1.
// Conflict-free on all passes (X1 write 4x STS.128; R2 read/write; R3 read).
// Loads use DEFAULT cache policy (input ~134MB nearly fits 126MB L2 across
// graph replays); stores use .cs to stay evict-first. No launch_bounds cap:
// natural regs -> 5 CTAs/SM (6 was shown to regress via L1TEX queue contention).

#define FWHT_N 4096
#define TPB    256

__device__ __forceinline__ void butterfly16(float v[16]) {
#pragma unroll
    for (int b = 1; b < 16; b <<= 1) {
#pragma unroll
        for (int k = 0; k < 16; k++) {
            if (!(k & b)) {
                float a = v[k];
                float c = v[k | b];
                v[k]     = a + c;
                v[k | b] = a - c;
            }
        }
    }
}

__global__ __launch_bounds__(TPB)
void QHadamard_40243843564239_kernel(const float* __restrict__ x,
                                     float* __restrict__ out) {
    __shared__ __half2 s[FWHT_N];   // 16 KB

    const int t = threadIdx.x;
    const int i = t & 15;
    const int w = t >> 4;
    const int wbit = w & 1;

    const size_t row0 = (size_t)blockIdx.x * 2;
    const float* __restrict__ xin0  = x   + row0 * FWHT_N;
    const float* __restrict__ xin1  = xin0 + FWHT_N;
    float* __restrict__       yout0 = out + row0 * FWHT_N;
    float* __restrict__       yout1 = yout0 + FWHT_N;

    float v0[16], v1[16];

    // ---- Round 1: bits 0..3 in regs. e = 16t + k. 8x LDG.128 front-batched.
    // Default cache policy: let input stay L2-resident across graph replays.
    {
        const float4* __restrict__ a4 = reinterpret_cast<const float4*>(xin0 + 16 * t);
        const float4* __restrict__ b4 = reinterpret_cast<const float4*>(xin1 + 16 * t);
        float4 fa[4], fb[4];
#pragma unroll
        for (int q = 0; q < 4; q++) fa[q] = a4[q];
#pragma unroll
        for (int q = 0; q < 4; q++) fb[q] = b4[q];
#pragma unroll
        for (int q = 0; q < 4; q++) {
            v0[4*q+0] = fa[q].x; v0[4*q+1] = fa[q].y; v0[4*q+2] = fa[q].z; v0[4*q+3] = fa[q].w;
            v1[4*q+0] = fb[q].x; v1[4*q+1] = fb[q].y; v1[4*q+2] = fb[q].z; v1[4*q+3] = fb[q].w;
        }
    }
    butterfly16(v0);
    butterfly16(v1);

    // ---- X1 write: 4x STS.128 (uint4 = 4 half2 slots = elems 4q..4q+3). ----
    // unit index u = 4*t' + (q ^ ((t>>1)&3)),  t' = t ^ ((t>>4)&1).
    {
        uint4* s16 = reinterpret_cast<uint4*>(s);
        const int tp   = t ^ ((t >> 4) & 1);
        const int swz  = (t >> 1) & 3;
        const int base = 4 * tp;
#pragma unroll
        for (int q = 0; q < 4; q++) {
            __half2 h0 = __floats2half2_rn(v0[4*q+0], v1[4*q+0]);
            __half2 h1 = __floats2half2_rn(v0[4*q+1], v1[4*q+1]);
            __half2 h2 = __floats2half2_rn(v0[4*q+2], v1[4*q+2]);
            __half2 h3 = __floats2half2_rn(v0[4*q+3], v1[4*q+3]);
            uint4 u;
            u.x = *reinterpret_cast<unsigned*>(&h0);
            u.y = *reinterpret_cast<unsigned*>(&h1);
            u.z = *reinterpret_cast<unsigned*>(&h2);
            u.w = *reinterpret_cast<unsigned*>(&h3);
            s16[base + (q ^ swz)] = u;
        }
    }
    __syncthreads();

    // ---- Round 2: bits 4..7 in regs. e = i + 16j + 256w. ----
    // S1 = (i&3) + 4*((i>>2) ^ ((j>>1)&3)) + 16*(j ^ wbit) + 256*w   (CF)
    // Read, butterfly, write back to the SAME thread-private addresses:
    // no barrier between read and write.
    {
        const int ilo = i & 3;
        const int ihi = i >> 2;
        const int base = 256 * w;
#pragma unroll
        for (int j = 0; j < 16; j++) {
            const int idx = ilo + ((ihi ^ ((j >> 1) & 3)) << 2) + ((j ^ wbit) << 4) + base;
            float2 f = __half22float2(s[idx]);
            v0[j] = f.x;
            v1[j] = f.y;
        }
        butterfly16(v0);
        butterfly16(v1);
#pragma unroll
        for (int j = 0; j < 16; j++) {
            const int idx = ilo + ((ihi ^ ((j >> 1) & 3)) << 2) + ((j ^ wbit) << 4) + base;
            s[idx] = __floats2half2_rn(v0[j], v1[j]);
        }
    }
    __syncthreads();

    // ---- Round 3: bits 8..11 in regs. e = t + 256k, still in S1 layout. ----
    // S1(e): bits0-1 = t&3; bits2-3 = ((t>>2)&3) ^ ((t>>5)&3) (warp-constant);
    //        bit4 = ((t>>4)&1) ^ (k&1); bits5+ = (t & ~31) + 256k.  (CF)
    {
        const int lo  = (t & 3) + ((((t >> 2) & 3) ^ ((t >> 5) & 3)) << 2);
        const int b4  = (t >> 4) & 1;
        const int hi  = (t & ~31);
#pragma unroll
        for (int k = 0; k < 16; k++) {
            const int idx = lo + ((b4 ^ (k & 1)) << 4) + hi + (k << 8);
            float2 f = __half22float2(s[idx]);
            v0[k] = f.x;
            v1[k] = f.y;
        }
    }
    butterfly16(v0);
    butterfly16(v1);

    // ---- Store: coalesced streaming STG.32 per row (evict-first in L2). ----
    const float scale = 0.015625f;   // 1/sqrt(4096)
#pragma unroll
    for (int k = 0; k < 16; k++) {
        __stcs(&yout0[t + 256 * k], v0[k] * scale);
        __stcs(&yout1[t + 256 * k], v1[k] * scale);
    }
}

extern "C" void kernel_launch(void* const* d_in, const int* in_sizes, int n_in,
                              void* d_out, int out_size) {
    const float* x = (const float*)d_in[0];
    float* out = (float*)d_out;
    const int rows = in_sizes[0] / FWHT_N;   // 8192
    QHadamard_40243843564239_kernel<<<rows / 2, TPB>>>(x, out);
}